// round 4
// baseline (speedup 1.0000x reference)
#include <cuda_runtime.h>

// ---------------- scratch (device globals; no allocations allowed) ----------
// token layout: [B=8][N=1024][M=512] row-major
//   N = (hp&15)*64 + pw*8 + ph ; M = cq*64 + wp*2 + (hp>>4)
//   where pixel (w,h): wp=w>>3, pw=w&7, hp=h>>3, ph=h&7
static __device__ float g_q[8u * 1024 * 512];
static __device__ float g_k[8u * 1024 * 512];
static __device__ float g_v[8u * 1024 * 512];
// energy / attn: [B=8][N=1024][N=1024]
static __device__ float g_e[8u * 1024 * 1024];
// O[n'][m] = sum_n attn[n'][n] * V[n][m]; flat per batch == [Cq=8][W=256][H=256]
static __device__ float g_o[8u * 1024 * 512];

// ---------------- kernel 1: fused QKV 1x1 conv -> patch-token layout --------
__global__ __launch_bounds__(256) void qkv_kernel(
    const float* __restrict__ x,
    const float* __restrict__ Wq, const float* __restrict__ bq,
    const float* __restrict__ Wk, const float* __restrict__ bk,
    const float* __restrict__ Wv, const float* __restrict__ bv)
{
    __shared__ __align__(16) float sWq[512], sWk[512], sWv[512];
    __shared__ float sb[24];
    int tid = threadIdx.x;
    for (int i = tid; i < 512; i += 256) {
        int cq = i & 7, c = i >> 3;           // transposed: sW[c*8 + cq]
        sWq[i] = Wq[cq * 64 + c];
        sWk[i] = Wk[cq * 64 + c];
        sWv[i] = Wv[cq * 64 + c];
    }
    if (tid < 8) { sb[tid] = bq[tid]; sb[8 + tid] = bk[tid]; sb[16 + tid] = bv[tid]; }
    __syncthreads();

    int t = blockIdx.x * 256 + tid;           // 0 .. 8*65536-1
    int b = t >> 16;
    int p = t & 65535;
    const float* xp = x + ((size_t)b << 22) + p;

    float aq[8], ak[8], av[8];
    #pragma unroll
    for (int i = 0; i < 8; i++) { aq[i] = sb[i]; ak[i] = sb[8 + i]; av[i] = sb[16 + i]; }

    #pragma unroll 8
    for (int c = 0; c < 64; c++) {
        float xv = __ldg(xp + ((size_t)c << 16));
        float4 q0 = *(const float4*)(sWq + c * 8);
        float4 q1 = *(const float4*)(sWq + c * 8 + 4);
        float4 k0 = *(const float4*)(sWk + c * 8);
        float4 k1 = *(const float4*)(sWk + c * 8 + 4);
        float4 v0 = *(const float4*)(sWv + c * 8);
        float4 v1 = *(const float4*)(sWv + c * 8 + 4);
        aq[0] += q0.x * xv; aq[1] += q0.y * xv; aq[2] += q0.z * xv; aq[3] += q0.w * xv;
        aq[4] += q1.x * xv; aq[5] += q1.y * xv; aq[6] += q1.z * xv; aq[7] += q1.w * xv;
        ak[0] += k0.x * xv; ak[1] += k0.y * xv; ak[2] += k0.z * xv; ak[3] += k0.w * xv;
        ak[4] += k1.x * xv; ak[5] += k1.y * xv; ak[6] += k1.z * xv; ak[7] += k1.w * xv;
        av[0] += v0.x * xv; av[1] += v0.y * xv; av[2] += v0.z * xv; av[3] += v0.w * xv;
        av[4] += v1.x * xv; av[5] += v1.y * xv; av[6] += v1.z * xv; av[7] += v1.w * xv;
    }

    // --- exact reference reshape semantics ---
    int w = p >> 8, h = p & 255;
    int wp = w >> 3, pw = w & 7, hp = h >> 3, ph = h & 7;
    int n     = ((hp & 15) << 6) + (pw << 3) + ph;   // token axis
    int mbase = (wp << 1) + (hp >> 4);               // feature axis (per cq block of 64)
    size_t base = (((size_t)b << 10) + n) * 512 + mbase;
    #pragma unroll
    for (int cq = 0; cq < 8; cq++) {
        g_q[base + cq * 64] = aq[cq];
        g_k[base + cq * 64] = ak[cq];
        g_v[base + cq * 64] = av[cq];
    }
}

// ---------------- SGEMM body: 128x128 tile, BK=8, 8x8 per thread -----------
// TRANS_B=true : C[i,j] = alpha * sum_k A[i,k] * B[j,k]   (both row-major, NT)
// TRANS_B=false: C[i,j] = alpha * sum_k A[i,k] * B[k,j]   (NN)
template <bool TRANS_B>
__device__ __forceinline__ void sgemm_body(
    const float* __restrict__ A, const float* __restrict__ B, float* __restrict__ C,
    int K, int lda, int ldb, int ldc, float alpha)
{
    __shared__ __align__(16) float As[8][132];
    __shared__ __align__(16) float Bs[8][132];

    int m0 = blockIdx.y * 128, n0 = blockIdx.x * 128;
    int tid = threadIdx.x;
    int ty = tid >> 4, tx = tid & 15;

    int ar = tid >> 1;             // 0..127
    int ac = (tid & 1) * 4;        // 0 or 4
    int br = TRANS_B ? ar : (tid >> 5);            // NT: row within n-tile ; NN: k-row 0..7
    int bc = TRANS_B ? ac : ((tid & 31) * 4);      // NT: k-offset        ; NN: col 0..124

    float acc[8][8];
    #pragma unroll
    for (int i = 0; i < 8; i++)
        #pragma unroll
        for (int j = 0; j < 8; j++) acc[i][j] = 0.f;

    int KB = K >> 3;
    float4 pa, pb;
    pa = *(const float4*)(A + (size_t)(m0 + ar) * lda + ac);
    if (TRANS_B) pb = *(const float4*)(B + (size_t)(n0 + br) * ldb + bc);
    else         pb = *(const float4*)(B + (size_t)br * ldb + n0 + bc);

    for (int kb = 0; kb < KB; kb++) {
        __syncthreads();
        As[ac + 0][ar] = pa.x; As[ac + 1][ar] = pa.y;
        As[ac + 2][ar] = pa.z; As[ac + 3][ar] = pa.w;
        if (TRANS_B) {
            Bs[bc + 0][br] = pb.x; Bs[bc + 1][br] = pb.y;
            Bs[bc + 2][br] = pb.z; Bs[bc + 3][br] = pb.w;
        } else {
            *(float4*)&Bs[br][bc] = pb;
        }
        __syncthreads();

        if (kb + 1 < KB) {
            int ko = (kb + 1) << 3;
            pa = *(const float4*)(A + (size_t)(m0 + ar) * lda + ko + ac);
            if (TRANS_B) pb = *(const float4*)(B + (size_t)(n0 + br) * ldb + ko + bc);
            else         pb = *(const float4*)(B + (size_t)(ko + br) * ldb + n0 + bc);
        }

        #pragma unroll
        for (int k = 0; k < 8; k++) {
            float4 a0 = *(const float4*)&As[k][ty * 8];
            float4 a1 = *(const float4*)&As[k][ty * 8 + 4];
            float4 b0 = *(const float4*)&Bs[k][tx * 8];
            float4 b1 = *(const float4*)&Bs[k][tx * 8 + 4];
            float ar8[8] = {a0.x, a0.y, a0.z, a0.w, a1.x, a1.y, a1.z, a1.w};
            float br8[8] = {b0.x, b0.y, b0.z, b0.w, b1.x, b1.y, b1.z, b1.w};
            #pragma unroll
            for (int i = 0; i < 8; i++)
                #pragma unroll
                for (int j = 0; j < 8; j++) acc[i][j] += ar8[i] * br8[j];
        }
    }

    #pragma unroll
    for (int i = 0; i < 8; i++) {
        float* crow = C + (size_t)(m0 + ty * 8 + i) * ldc + n0 + tx * 8;
        float4 o0 = {acc[i][0] * alpha, acc[i][1] * alpha, acc[i][2] * alpha, acc[i][3] * alpha};
        float4 o1 = {acc[i][4] * alpha, acc[i][5] * alpha, acc[i][6] * alpha, acc[i][7] * alpha};
        *(float4*)crow = o0;
        *(float4*)(crow + 4) = o1;
    }
}

// energy = (1/32) * Q @ K^T  : per batch [1024,512] x [1024,512]^T -> [1024,1024]
__global__ __launch_bounds__(256) void gemm_qk_kernel()
{
    size_t b = blockIdx.z;
    sgemm_body<true>(g_q + b * (1024u * 512), g_k + b * (1024u * 512),
                     g_e + b * (1024u * 1024),
                     512, 512, 512, 1024, 1.0f / 32.0f);
}

// O = attn @ V : per batch [1024,1024] x [1024,512] -> [1024,512]
__global__ __launch_bounds__(256) void gemm_av_kernel()
{
    size_t b = blockIdx.z;
    sgemm_body<false>(g_e + b * (1024u * 1024), g_v + b * (1024u * 512),
                      g_o + b * (1024u * 512),
                      1024, 1024, 512, 512, 1.0f);
}

// ---------------- kernel 3: row softmax over g_e (8192 rows x 1024) --------
__global__ __launch_bounds__(256) void softmax_kernel()
{
    size_t row = blockIdx.x;
    float* r = g_e + row * 1024;
    int tid = threadIdx.x;
    int wid = tid >> 5, lid = tid & 31;
    __shared__ float sm[8], ss[8];

    float4 v = ((float4*)r)[tid];
    float m = fmaxf(fmaxf(v.x, v.y), fmaxf(v.z, v.w));
    #pragma unroll
    for (int o = 16; o; o >>= 1) m = fmaxf(m, __shfl_xor_sync(0xffffffffu, m, o));
    if (lid == 0) sm[wid] = m;
    __syncthreads();
    m = sm[0];
    #pragma unroll
    for (int i = 1; i < 8; i++) m = fmaxf(m, sm[i]);

    v.x = __expf(v.x - m); v.y = __expf(v.y - m);
    v.z = __expf(v.z - m); v.w = __expf(v.w - m);
    float s = (v.x + v.y) + (v.z + v.w);
    #pragma unroll
    for (int o = 16; o; o >>= 1) s += __shfl_xor_sync(0xffffffffu, s, o);
    if (lid == 0) ss[wid] = s;
    __syncthreads();
    s = ss[0];
    #pragma unroll
    for (int i = 1; i < 8; i++) s += ss[i];

    float inv = 1.0f / s;
    v.x *= inv; v.y *= inv; v.z *= inv; v.w *= inv;
    ((float4*)r)[tid] = v;
}

// ---------------- kernel 5: out = gamma * (Wo @ O + bo) + x -----------------
// g_o flat per batch IS [Cq=8][W=256][H=256]:
//   O[n'][m] with n'=cq*128+(w>>1), m=(w&1)*256+h  ->  flat = cq*65536 + w*256 + h.
__global__ __launch_bounds__(256) void epilogue_kernel(
    const float* __restrict__ x, const float* __restrict__ Wo,
    const float* __restrict__ bo, const float* __restrict__ gamma,
    float* __restrict__ out)
{
    __shared__ __align__(16) float sWo[512];   // [o][cq], as given (row-major 64x8)
    __shared__ float sbo[64];
    int tid = threadIdx.x;
    for (int i = tid; i < 512; i += 256) sWo[i] = Wo[i];
    if (tid < 64) sbo[tid] = bo[tid];
    __syncthreads();
    float g = __ldg(gamma);

    int t = blockIdx.x * 256 + tid;
    int b = t >> 16;
    int p = t & 65535;

    float ov[8];
    size_t obase = ((size_t)b << 19) + p;
    #pragma unroll
    for (int cq = 0; cq < 8; cq++) ov[cq] = g_o[obase + ((size_t)cq << 16)];

    size_t xbase = ((size_t)b << 22) + p;
    #pragma unroll 8
    for (int o = 0; o < 64; o++) {
        float4 w0 = *(const float4*)(sWo + o * 8);
        float4 w1 = *(const float4*)(sWo + o * 8 + 4);
        float a = sbo[o];
        a += w0.x * ov[0] + w0.y * ov[1] + w0.z * ov[2] + w0.w * ov[3];
        a += w1.x * ov[4] + w1.y * ov[5] + w1.z * ov[6] + w1.w * ov[7];
        size_t idx = xbase + ((size_t)o << 16);
        out[idx] = g * a + __ldg(x + idx);
    }
}

// ---------------- launch ----------------------------------------------------
extern "C" void kernel_launch(void* const* d_in, const int* in_sizes, int n_in,
                              void* d_out, int out_size)
{
    const float* x     = (const float*)d_in[0];
    const float* Wq    = (const float*)d_in[1];
    const float* bq    = (const float*)d_in[2];
    const float* Wk    = (const float*)d_in[3];
    const float* bk    = (const float*)d_in[4];
    const float* Wv    = (const float*)d_in[5];
    const float* bv    = (const float*)d_in[6];
    const float* Wo    = (const float*)d_in[7];
    const float* bo    = (const float*)d_in[8];
    const float* gamma = (const float*)d_in[9];
    float* out = (float*)d_out;

    qkv_kernel<<<2048, 256>>>(x, Wq, bq, Wk, bk, Wv, bv);

    dim3 gqk(1024 / 128, 1024 / 128, 8);
    gemm_qk_kernel<<<gqk, 256>>>();

    softmax_kernel<<<8 * 1024, 256>>>();

    dim3 gav(512 / 128, 1024 / 128, 8);
    gemm_av_kernel<<<gav, 256>>>();

    epilogue_kernel<<<2048, 256>>>(x, Wo, bo, gamma, out);
}

// round 6
// speedup vs baseline: 2.3475x; 2.3475x over previous
#include <cuda_runtime.h>
#include <cuda_bf16.h>
#include <cstdint>

// ================= helpers ==================================================
__device__ __forceinline__ uint32_t smem_u32(const void* p) {
    uint32_t a;
    asm("{ .reg .u64 t; cvta.to.shared.u64 t, %1; cvt.u32.u64 %0, t; }" : "=r"(a) : "l"(p));
    return a;
}
#define CP16(s, g)   asm volatile("cp.async.cg.shared.global [%0], [%1], 16;" :: "r"(s), "l"(g))
#define CP_COMMIT()  asm volatile("cp.async.commit_group;" ::: "memory")
#define CP_WAIT2()   asm volatile("cp.async.wait_group 2;" ::: "memory")

__device__ __forceinline__ void ldsm4(uint32_t& r0, uint32_t& r1, uint32_t& r2, uint32_t& r3, uint32_t a) {
    asm volatile("ldmatrix.sync.aligned.m8n8.x4.shared.b16 {%0,%1,%2,%3}, [%4];"
        : "=r"(r0), "=r"(r1), "=r"(r2), "=r"(r3) : "r"(a));
}
__device__ __forceinline__ void mma_bf16(float* c, const uint32_t* a, const uint32_t* b) {
    asm volatile("mma.sync.aligned.m16n8k16.row.col.f32.bf16.bf16.f32 "
        "{%0,%1,%2,%3}, {%4,%5,%6,%7}, {%8,%9}, {%0,%1,%2,%3};"
        : "+f"(c[0]), "+f"(c[1]), "+f"(c[2]), "+f"(c[3])
        : "r"(a[0]), "r"(a[1]), "r"(a[2]), "r"(a[3]), "r"(b[0]), "r"(b[1]));
}

// ================= scratch (device globals) =================================
static __device__ __nv_bfloat16 g_qb[8u * 1024 * 512];
static __device__ __nv_bfloat16 g_kb[8u * 1024 * 512];
static __device__ __nv_bfloat16 g_vtok[8u * 1024 * 512];   // [n][m]
static __device__ __nv_bfloat16 g_vt[8u * 512 * 1024];     // [m][n]
static __device__ float         g_e[8u * 1024 * 1024];     // fp32 energy
static __device__ __nv_bfloat16 g_attn[8u * 1024 * 1024];  // bf16 attn
static __device__ float         g_o[8u * 1024 * 512];      // == [Cq][W][H]

// ================= kernel 1: fused QKV conv -> bf16 token layout ============
__global__ __launch_bounds__(256) void qkv_kernel(
    const float* __restrict__ x,
    const float* __restrict__ Wq, const float* __restrict__ bq,
    const float* __restrict__ Wk, const float* __restrict__ bk,
    const float* __restrict__ Wv, const float* __restrict__ bv)
{
    __shared__ __align__(16) float sWq[512], sWk[512], sWv[512];
    __shared__ float sb[24];
    int tid = threadIdx.x;
    for (int i = tid; i < 512; i += 256) {
        int cq = i & 7, c = i >> 3;          // transposed: sW[c*8+cq]
        sWq[i] = Wq[cq * 64 + c];
        sWk[i] = Wk[cq * 64 + c];
        sWv[i] = Wv[cq * 64 + c];
    }
    if (tid < 8) { sb[tid] = bq[tid]; sb[8 + tid] = bk[tid]; sb[16 + tid] = bv[tid]; }
    __syncthreads();

    int t = blockIdx.x * 256 + tid;          // 0 .. 8*32768-1
    int b = t >> 15;
    int r = t & 32767;
    int w = r >> 7, h = r & 127;             // h in [0,128); pair is h and h+128
    const float* xp = x + ((size_t)b << 22) + (w << 8) + h;

    float a0[24], a1[24];
    #pragma unroll
    for (int i = 0; i < 24; i++) { a0[i] = sb[i]; a1[i] = sb[i]; }

    #pragma unroll 4
    for (int c = 0; c < 64; c++) {
        float xl = __ldg(xp + ((size_t)c << 16));
        float xh = __ldg(xp + ((size_t)c << 16) + 128);
        #pragma unroll
        for (int cq = 0; cq < 8; cq++) {
            float wq = sWq[c * 8 + cq], wk = sWk[c * 8 + cq], wv = sWv[c * 8 + cq];
            a0[cq]      += wq * xl;  a1[cq]      += wq * xh;
            a0[8 + cq]  += wk * xl;  a1[8 + cq]  += wk * xh;
            a0[16 + cq] += wv * xl;  a1[16 + cq] += wv * xh;
        }
    }

    int n  = ((h >> 3) << 6) | ((w & 7) << 3) | (h & 7);
    int mb = (w >> 3) << 1;
    size_t half = (((((size_t)b << 10) | n) << 9) + mb) >> 1;
    __nv_bfloat162* qp = (__nv_bfloat162*)g_qb;
    __nv_bfloat162* kp = (__nv_bfloat162*)g_kb;
    __nv_bfloat162* vp = (__nv_bfloat162*)g_vtok;
    #pragma unroll
    for (int cq = 0; cq < 8; cq++) {
        __nv_bfloat162 q2, k2, v2;
        q2.x = __float2bfloat16_rn(a0[cq]);      q2.y = __float2bfloat16_rn(a1[cq]);
        k2.x = __float2bfloat16_rn(a0[8 + cq]);  k2.y = __float2bfloat16_rn(a1[8 + cq]);
        v2.x = __float2bfloat16_rn(a0[16 + cq]); v2.y = __float2bfloat16_rn(a1[16 + cq]);
        qp[half + cq * 32] = q2;
        kp[half + cq * 32] = k2;
        vp[half + cq * 32] = v2;
    }
}

// ================= kernel 2: V transpose [n][m] -> [m][n] (bf16) ============
__global__ __launch_bounds__(256) void vt_kernel()
{
    __shared__ unsigned short s[64][66];
    int b = blockIdx.z, n0 = blockIdx.y * 64, m0 = blockIdx.x * 64;
    int tid = threadIdx.x;
    const unsigned short* src = (const unsigned short*)g_vtok + ((size_t)b << 19);
    unsigned short* dst = (unsigned short*)g_vt + ((size_t)b << 19);

    #pragma unroll
    for (int i = 0; i < 2; i++) {
        int q = i * 256 + tid;
        int r = q >> 3, c = (q & 7) << 3;
        uint4 v = *(const uint4*)(src + (size_t)(n0 + r) * 512 + m0 + c);
        uint32_t* row = (uint32_t*)&s[r][c];
        row[0] = v.x; row[1] = v.y; row[2] = v.z; row[3] = v.w;
    }
    __syncthreads();
    #pragma unroll
    for (int i = 0; i < 2; i++) {
        int q = i * 256 + tid;
        int rm = q >> 3, cn = (q & 7) << 3;
        uint32_t o[4];
        #pragma unroll
        for (int k = 0; k < 4; k++)
            o[k] = (uint32_t)s[cn + 2 * k][rm] | ((uint32_t)s[cn + 2 * k + 1][rm] << 16);
        uint4 v = {o[0], o[1], o[2], o[3]};
        *(uint4*)(dst + (size_t)(m0 + rm) * 1024 + n0 + cn) = v;
    }
}

// ================= HMMA bf16 NT GEMM: C = alpha * A @ B^T ===================
// A: [Mtot,K] bf16 rows K-major; B: [Ntot,K] bf16 rows K-major; C fp32.
// 128x128 block, BK=32, 3-stage cp.async pipeline, 8 warps (2x4), 64x32/warp.
static constexpr int HLDT  = 40;                 // padded smem row, bf16 units
static constexpr int HSTG  = 128 * HLDT * 2;     // 10240 B per tile per stage
static constexpr int HBOFF = 3 * HSTG;           // B tiles after 3 A stages
static constexpr int HSMEM = 6 * HSTG;           // 61440 B

template <int K, int LDA, int LDB, int LDC, long SA, long SB, long SC>
__device__ __forceinline__ void hgemm_body(
    const __nv_bfloat16* __restrict__ A, const __nv_bfloat16* __restrict__ B,
    float* __restrict__ C, float alpha)
{
    extern __shared__ __align__(16) char smem[];
    uint32_t sbase = smem_u32(smem);
    int tid = threadIdx.x, lane = tid & 31, wid = tid >> 5;
    int wm = wid & 1, wn = wid >> 1;            // 2 x 4 warp grid
    A += (size_t)blockIdx.z * SA;
    B += (size_t)blockIdx.z * SB;
    C += (size_t)blockIdx.z * SC;
    int m0 = blockIdx.y * 128, n0 = blockIdx.x * 128;

    auto issue = [&](int s) {
        int buf = s % 3;
        int k0 = s * 32;
        #pragma unroll
        for (int i = 0; i < 4; i++) {
            int c = i * 256 + tid;              // 0..1023 chunk id (16B each)
            int isB = c >> 9;
            int cc = c & 511;
            int row = cc >> 2;
            int col = (cc & 3) << 3;            // bf16 col
            const __nv_bfloat16* g = isB
                ? B + (size_t)(n0 + row) * LDB + k0 + col
                : A + (size_t)(m0 + row) * LDA + k0 + col;
            uint32_t sa = sbase + (isB ? HBOFF : 0) + buf * HSTG + (row * HLDT + col) * 2;
            CP16(sa, g);
        }
        CP_COMMIT();
    };

    constexpr int S = K / 32;
    issue(0); issue(1); issue(2);

    float acc[4][4][4];
    #pragma unroll
    for (int mt = 0; mt < 4; mt++)
        #pragma unroll
        for (int nt = 0; nt < 4; nt++)
            #pragma unroll
            for (int r = 0; r < 4; r++) acc[mt][nt][r] = 0.f;

    uint32_t a_off = ((wm * 64 + (lane & 15)) * HLDT + (lane >> 4) * 8) * 2;
    uint32_t b_off = ((wn * 32 + (lane & 15)) * HLDT + (lane >> 4) * 8) * 2;

    for (int s = 0; s < S; s++) {
        int buf = s % 3;
        CP_WAIT2();
        __syncthreads();
        uint32_t abase = sbase + buf * HSTG + a_off;
        uint32_t bbase = sbase + HBOFF + buf * HSTG + b_off;
        #pragma unroll
        for (int kk = 0; kk < 2; kk++) {
            uint32_t a[4][4], bfr[4][2];
            #pragma unroll
            for (int mt = 0; mt < 4; mt++)
                ldsm4(a[mt][0], a[mt][1], a[mt][2], a[mt][3],
                      abase + (mt * 16 * HLDT + kk * 16) * 2);
            #pragma unroll
            for (int np = 0; np < 2; np++) {
                uint32_t t0, t1, t2, t3;
                ldsm4(t0, t1, t2, t3, bbase + (np * 16 * HLDT + kk * 16) * 2);
                bfr[2 * np][0] = t0;     bfr[2 * np][1] = t2;
                bfr[2 * np + 1][0] = t1; bfr[2 * np + 1][1] = t3;
            }
            #pragma unroll
            for (int mt = 0; mt < 4; mt++)
                #pragma unroll
                for (int nt = 0; nt < 4; nt++)
                    mma_bf16(acc[mt][nt], a[mt], bfr[nt]);
        }
        __syncthreads();
        if (s + 3 < S) issue(s + 3); else CP_COMMIT();
    }

    int rbase = m0 + wm * 64 + (lane >> 2);
    int cbase = n0 + wn * 32 + (lane & 3) * 2;
    #pragma unroll
    for (int mt = 0; mt < 4; mt++)
        #pragma unroll
        for (int nt = 0; nt < 4; nt++) {
            float2 v0 = { acc[mt][nt][0] * alpha, acc[mt][nt][1] * alpha };
            float2 v1 = { acc[mt][nt][2] * alpha, acc[mt][nt][3] * alpha };
            *(float2*)&C[(size_t)(rbase + mt * 16) * LDC + cbase + nt * 8] = v0;
            *(float2*)&C[(size_t)(rbase + mt * 16 + 8) * LDC + cbase + nt * 8] = v1;
        }
}

// energy = (1/32) Q @ K^T : [1024,512] x [1024,512]^T per batch
__global__ __launch_bounds__(256, 2) void gemm_qk_kernel()
{
    hgemm_body<512, 512, 512, 1024, 1024l * 512, 1024l * 512, 1024l * 1024>(
        g_qb, g_kb, g_e, 1.0f / 32.0f);
}
// O = attn @ Vt^T : [1024,1024] x [512,1024]^T per batch
__global__ __launch_bounds__(256, 2) void gemm_av_kernel()
{
    hgemm_body<1024, 1024, 1024, 512, 1024l * 1024, 512l * 1024, 1024l * 512>(
        g_attn, g_vt, g_o, 1.0f);
}

// ================= kernel 4: softmax fp32 -> bf16 attn ======================
__global__ __launch_bounds__(256) void softmax_kernel()
{
    size_t row = blockIdx.x;
    const float* r = g_e + row * 1024;
    int tid = threadIdx.x, wid = tid >> 5, lid = tid & 31;
    __shared__ float sm[8], ss[8];

    float4 v = ((const float4*)r)[tid];
    float m = fmaxf(fmaxf(v.x, v.y), fmaxf(v.z, v.w));
    #pragma unroll
    for (int o = 16; o; o >>= 1) m = fmaxf(m, __shfl_xor_sync(0xffffffffu, m, o));
    if (lid == 0) sm[wid] = m;
    __syncthreads();
    m = sm[0];
    #pragma unroll
    for (int i = 1; i < 8; i++) m = fmaxf(m, sm[i]);

    v.x = __expf(v.x - m); v.y = __expf(v.y - m);
    v.z = __expf(v.z - m); v.w = __expf(v.w - m);
    float s = (v.x + v.y) + (v.z + v.w);
    #pragma unroll
    for (int o = 16; o; o >>= 1) s += __shfl_xor_sync(0xffffffffu, s, o);
    if (lid == 0) ss[wid] = s;
    __syncthreads();
    s = ss[0];
    #pragma unroll
    for (int i = 1; i < 8; i++) s += ss[i];

    float inv = 1.0f / s;
    __nv_bfloat162 o0, o1;
    o0.x = __float2bfloat16_rn(v.x * inv); o0.y = __float2bfloat16_rn(v.y * inv);
    o1.x = __float2bfloat16_rn(v.z * inv); o1.y = __float2bfloat16_rn(v.w * inv);
    __nv_bfloat162* op = (__nv_bfloat162*)(g_attn + row * 1024) + 2 * tid;
    op[0] = o0; op[1] = o1;
}

// ================= kernel 6: out = gamma*(Wo @ O + bo) + x ==================
__global__ __launch_bounds__(256) void epilogue_kernel(
    const float* __restrict__ x, const float* __restrict__ Wo,
    const float* __restrict__ bo, const float* __restrict__ gamma,
    float* __restrict__ out)
{
    __shared__ __align__(16) float sWo[512];
    __shared__ float sbo[64];
    int tid = threadIdx.x;
    for (int i = tid; i < 512; i += 256) sWo[i] = Wo[i];
    if (tid < 64) sbo[tid] = bo[tid];
    __syncthreads();
    float g = __ldg(gamma);

    int t = blockIdx.x * 256 + tid;
    int b = t >> 16;
    int p = t & 65535;

    float ov[8];
    size_t obase = ((size_t)b << 19) + p;
    #pragma unroll
    for (int cq = 0; cq < 8; cq++) ov[cq] = g_o[obase + ((size_t)cq << 16)];

    size_t xbase = ((size_t)b << 22) + p;
    #pragma unroll 8
    for (int o = 0; o < 64; o++) {
        float4 w0 = *(const float4*)(sWo + o * 8);
        float4 w1 = *(const float4*)(sWo + o * 8 + 4);
        float a = sbo[o];
        a += w0.x * ov[0] + w0.y * ov[1] + w0.z * ov[2] + w0.w * ov[3];
        a += w1.x * ov[4] + w1.y * ov[5] + w1.z * ov[6] + w1.w * ov[7];
        size_t idx = xbase + ((size_t)o << 16);
        out[idx] = g * a + __ldg(x + idx);
    }
}

// ================= launch ===================================================
extern "C" void kernel_launch(void* const* d_in, const int* in_sizes, int n_in,
                              void* d_out, int out_size)
{
    const float* x     = (const float*)d_in[0];
    const float* Wq    = (const float*)d_in[1];
    const float* bq    = (const float*)d_in[2];
    const float* Wk    = (const float*)d_in[3];
    const float* bk    = (const float*)d_in[4];
    const float* Wv    = (const float*)d_in[5];
    const float* bv    = (const float*)d_in[6];
    const float* Wo    = (const float*)d_in[7];
    const float* bo    = (const float*)d_in[8];
    const float* gamma = (const float*)d_in[9];
    float* out = (float*)d_out;

    cudaFuncSetAttribute(gemm_qk_kernel, cudaFuncAttributeMaxDynamicSharedMemorySize, HSMEM);
    cudaFuncSetAttribute(gemm_av_kernel, cudaFuncAttributeMaxDynamicSharedMemorySize, HSMEM);

    qkv_kernel<<<1024, 256>>>(x, Wq, bq, Wk, bk, Wv, bv);

    dim3 gvt(8, 16, 8);
    vt_kernel<<<gvt, 256>>>();

    dim3 gqk(8, 8, 8);
    gemm_qk_kernel<<<gqk, 256, HSMEM>>>();

    softmax_kernel<<<8 * 1024, 256>>>();

    dim3 gav(4, 8, 8);
    gemm_av_kernel<<<gav, 256, HSMEM>>>();

    epilogue_kernel<<<2048, 256>>>(x, Wo, bo, gamma, out);
}

// round 11
// speedup vs baseline: 3.2364x; 1.3787x over previous
#include <cuda_runtime.h>
#include <cuda_bf16.h>
#include <cstdint>

// ================= helpers ==================================================
__device__ __forceinline__ uint32_t smem_u32(const void* p) {
    uint32_t a;
    asm("{ .reg .u64 t; cvta.to.shared.u64 t, %1; cvt.u32.u64 %0, t; }" : "=r"(a) : "l"(p));
    return a;
}
#define CP16(s, g)   asm volatile("cp.async.cg.shared.global [%0], [%1], 16;" :: "r"(s), "l"(g))
#define CP_COMMIT()  asm volatile("cp.async.commit_group;" ::: "memory")
#define CP_WAIT2()   asm volatile("cp.async.wait_group 2;" ::: "memory")

__device__ __forceinline__ void ldsm4(uint32_t& r0, uint32_t& r1, uint32_t& r2, uint32_t& r3, uint32_t a) {
    asm volatile("ldmatrix.sync.aligned.m8n8.x4.shared.b16 {%0,%1,%2,%3}, [%4];"
        : "=r"(r0), "=r"(r1), "=r"(r2), "=r"(r3) : "r"(a));
}
__device__ __forceinline__ void mma_bf16(float* c, const uint32_t* a, const uint32_t* b) {
    asm volatile("mma.sync.aligned.m16n8k16.row.col.f32.bf16.bf16.f32 "
        "{%0,%1,%2,%3}, {%4,%5,%6,%7}, {%8,%9}, {%0,%1,%2,%3};"
        : "+f"(c[0]), "+f"(c[1]), "+f"(c[2]), "+f"(c[3])
        : "r"(a[0]), "r"(a[1]), "r"(a[2]), "r"(a[3]), "r"(b[0]), "r"(b[1]));
}

// ================= scratch (device globals) =================================
static __device__ __nv_bfloat16 g_qb[8u * 1024 * 512];    // [b][n][m]
static __device__ __nv_bfloat16 g_kb[8u * 1024 * 512];    // [b][n][m]
static __device__ __nv_bfloat16 g_vmn[8u * 512 * 1024];   // [b][m][n]
static __device__ __nv_bfloat16 g_eb[8u * 1024 * 1024];   // bf16 energy
static __device__ __nv_bfloat16 g_attn[8u * 1024 * 1024]; // bf16 attn
static __device__ float         g_o[8u * 1024 * 512];     // == [Cq][W][H]

// ================= kernel 1: fused QKV conv (HFMA2, coalesced stores) =======
// block = (pw, wp0 in {0,8,16,24}, h0 in {0,32,64,96}, b); thread = (wp_i, hl).
// pixel pair (w, h) and (w, h+128): same token n, features (m, m+1).
__global__ __launch_bounds__(256) void qkv_kernel(
    const float* __restrict__ x,
    const float* __restrict__ Wq, const float* __restrict__ bq,
    const float* __restrict__ Wk, const float* __restrict__ bk,
    const float* __restrict__ Wv, const float* __restrict__ bv)
{
    __shared__ __align__(16) __nv_bfloat162 sW2[3][64][8];  // [tensor][c][cq] broadcast
    __shared__ __nv_bfloat162 sb2[24];
    __shared__ __nv_bfloat162 st[3][32][17];
    int tid = threadIdx.x;
    for (int i = tid; i < 512; i += 256) {
        int c = i >> 3, cq = i & 7;
        sW2[0][c][cq] = __float2bfloat162_rn(Wq[cq * 64 + c]);
        sW2[1][c][cq] = __float2bfloat162_rn(Wk[cq * 64 + c]);
        sW2[2][c][cq] = __float2bfloat162_rn(Wv[cq * 64 + c]);
    }
    if (tid < 24) {
        const float* bp = tid < 8 ? bq : (tid < 16 ? bk : bv);
        sb2[tid] = __float2bfloat162_rn(bp[tid & 7]);
    }
    __syncthreads();

    int b   = blockIdx.z;
    int pw  = blockIdx.x;
    int wp0 = (blockIdx.y & 3) * 8;
    int h0  = (blockIdx.y >> 2) * 32;
    int wp_i = tid >> 5, hl = tid & 31;
    int w = (wp0 + wp_i) * 8 + pw;
    int h = h0 + hl;
    const float* xp = x + ((size_t)b << 22) + (w << 8) + h;

    __nv_bfloat162 acc[24];
    #pragma unroll
    for (int i = 0; i < 24; i++) acc[i] = sb2[i];

    #pragma unroll 4
    for (int c = 0; c < 64; c++) {
        float xl = __ldg(xp + ((size_t)c << 16));
        float xh = __ldg(xp + ((size_t)c << 16) + 128);
        __nv_bfloat162 x2 = __floats2bfloat162_rn(xl, xh);
        uint4 uq0 = ((const uint4*)&sW2[0][c][0])[0];
        uint4 uq1 = ((const uint4*)&sW2[0][c][0])[1];
        uint4 uk0 = ((const uint4*)&sW2[1][c][0])[0];
        uint4 uk1 = ((const uint4*)&sW2[1][c][0])[1];
        uint4 uv0 = ((const uint4*)&sW2[2][c][0])[0];
        uint4 uv1 = ((const uint4*)&sW2[2][c][0])[1];
        #define B2(u) (*reinterpret_cast<const __nv_bfloat162*>(&(u)))
        acc[0]  = __hfma2(B2(uq0.x), x2, acc[0]);
        acc[1]  = __hfma2(B2(uq0.y), x2, acc[1]);
        acc[2]  = __hfma2(B2(uq0.z), x2, acc[2]);
        acc[3]  = __hfma2(B2(uq0.w), x2, acc[3]);
        acc[4]  = __hfma2(B2(uq1.x), x2, acc[4]);
        acc[5]  = __hfma2(B2(uq1.y), x2, acc[5]);
        acc[6]  = __hfma2(B2(uq1.z), x2, acc[6]);
        acc[7]  = __hfma2(B2(uq1.w), x2, acc[7]);
        acc[8]  = __hfma2(B2(uk0.x), x2, acc[8]);
        acc[9]  = __hfma2(B2(uk0.y), x2, acc[9]);
        acc[10] = __hfma2(B2(uk0.z), x2, acc[10]);
        acc[11] = __hfma2(B2(uk0.w), x2, acc[11]);
        acc[12] = __hfma2(B2(uk1.x), x2, acc[12]);
        acc[13] = __hfma2(B2(uk1.y), x2, acc[13]);
        acc[14] = __hfma2(B2(uk1.z), x2, acc[14]);
        acc[15] = __hfma2(B2(uk1.w), x2, acc[15]);
        acc[16] = __hfma2(B2(uv0.x), x2, acc[16]);
        acc[17] = __hfma2(B2(uv0.y), x2, acc[17]);
        acc[18] = __hfma2(B2(uv0.z), x2, acc[18]);
        acc[19] = __hfma2(B2(uv0.w), x2, acc[19]);
        acc[20] = __hfma2(B2(uv1.x), x2, acc[20]);
        acc[21] = __hfma2(B2(uv1.y), x2, acc[21]);
        acc[22] = __hfma2(B2(uv1.z), x2, acc[22]);
        acc[23] = __hfma2(B2(uv1.w), x2, acc[23]);
        #undef B2
    }

    // token base for this block: n = nb + (idx>>3)*64 + (idx&7), idx = hl
    int nb = (h0 >> 3) * 64 + pw * 8;
    int nn_w = tid >> 3, mm_w = tid & 7;            // Q/K writer mapping
    int n_qk = nb + ((nn_w >> 3) << 6) + (nn_w & 7);
    int mm_v = tid >> 5, nl_v = tid & 31;           // V writer mapping
    int n_v  = nb + ((nl_v >> 3) << 6) + (nl_v & 7);

    __nv_bfloat162* qp = (__nv_bfloat162*)g_qb;
    __nv_bfloat162* kp = (__nv_bfloat162*)g_kb;
    __nv_bfloat16*  vp = g_vmn;

    #pragma unroll
    for (int cq = 0; cq < 8; cq++) {
        __syncthreads();
        st[0][hl][wp_i] = acc[cq];
        st[1][hl][wp_i] = acc[8 + cq];
        st[2][hl][wp_i] = acc[16 + cq];
        __syncthreads();
        // Q/K: [n][m] bf162 units; m/2 = cq*32 + wp0 + mm
        size_t qkaddr = (((size_t)b << 10) + n_qk) * 256 + cq * 32 + wp0 + mm_w;
        qp[qkaddr] = st[0][nn_w][mm_w];
        kp[qkaddr] = st[1][nn_w][mm_w];
        // V: [m][n]; m = cq*64 + wp0*2 + 2*mm (+1)
        __nv_bfloat162 vv = st[2][nl_v][mm_v];
        size_t vaddr = (((size_t)b * 512) + cq * 64 + wp0 * 2 + 2 * mm_v) * 1024 + n_v;
        vp[vaddr]        = __low2bfloat16(vv);
        vp[vaddr + 1024] = __high2bfloat16(vv);
    }
}

// ================= HMMA bf16 NT GEMM: C = alpha * A @ B^T ===================
static constexpr int HLDT  = 40;
static constexpr int HSTG  = 128 * HLDT * 2;
static constexpr int HBOFF = 3 * HSTG;
static constexpr int HSMEM = 6 * HSTG;

template <int K, int LDA, int LDB, int LDC, long SA, long SB, long SC, typename OutT>
__device__ __forceinline__ void hgemm_body(
    const __nv_bfloat16* __restrict__ A, const __nv_bfloat16* __restrict__ B,
    OutT* __restrict__ C, float alpha)
{
    extern __shared__ __align__(16) char smem[];
    uint32_t sbase = smem_u32(smem);
    int tid = threadIdx.x, lane = tid & 31, wid = tid >> 5;
    int wm = wid & 1, wn = wid >> 1;
    A += (size_t)blockIdx.z * SA;
    B += (size_t)blockIdx.z * SB;
    C += (size_t)blockIdx.z * SC;
    int m0 = blockIdx.y * 128, n0 = blockIdx.x * 128;

    auto issue = [&](int s) {
        int buf = s % 3;
        int k0 = s * 32;
        #pragma unroll
        for (int i = 0; i < 4; i++) {
            int c = i * 256 + tid;
            int isB = c >> 9;
            int cc = c & 511;
            int row = cc >> 2;
            int col = (cc & 3) << 3;
            const __nv_bfloat16* g = isB
                ? B + (size_t)(n0 + row) * LDB + k0 + col
                : A + (size_t)(m0 + row) * LDA + k0 + col;
            uint32_t sa = sbase + (isB ? HBOFF : 0) + buf * HSTG + (row * HLDT + col) * 2;
            CP16(sa, g);
        }
        CP_COMMIT();
    };

    constexpr int S = K / 32;
    issue(0); issue(1); issue(2);

    float acc[4][4][4];
    #pragma unroll
    for (int mt = 0; mt < 4; mt++)
        #pragma unroll
        for (int nt = 0; nt < 4; nt++)
            #pragma unroll
            for (int r = 0; r < 4; r++) acc[mt][nt][r] = 0.f;

    uint32_t a_off = ((wm * 64 + (lane & 15)) * HLDT + (lane >> 4) * 8) * 2;
    uint32_t b_off = ((wn * 32 + (lane & 15)) * HLDT + (lane >> 4) * 8) * 2;

    for (int s = 0; s < S; s++) {
        int buf = s % 3;
        CP_WAIT2();
        __syncthreads();
        uint32_t abase = sbase + buf * HSTG + a_off;
        uint32_t bbase = sbase + HBOFF + buf * HSTG + b_off;
        #pragma unroll
        for (int kk = 0; kk < 2; kk++) {
            uint32_t a[4][4], bfr[4][2];
            #pragma unroll
            for (int mt = 0; mt < 4; mt++)
                ldsm4(a[mt][0], a[mt][1], a[mt][2], a[mt][3],
                      abase + (mt * 16 * HLDT + kk * 16) * 2);
            #pragma unroll
            for (int np = 0; np < 2; np++) {
                uint32_t t0, t1, t2, t3;
                ldsm4(t0, t1, t2, t3, bbase + (np * 16 * HLDT + kk * 16) * 2);
                bfr[2 * np][0] = t0;     bfr[2 * np][1] = t2;
                bfr[2 * np + 1][0] = t1; bfr[2 * np + 1][1] = t3;
            }
            #pragma unroll
            for (int mt = 0; mt < 4; mt++)
                #pragma unroll
                for (int nt = 0; nt < 4; nt++)
                    mma_bf16(acc[mt][nt], a[mt], bfr[nt]);
        }
        __syncthreads();
        if (s + 3 < S) issue(s + 3); else CP_COMMIT();
    }

    int rbase = m0 + wm * 64 + (lane >> 2);
    int cbase = n0 + wn * 32 + (lane & 3) * 2;
    #pragma unroll
    for (int mt = 0; mt < 4; mt++)
        #pragma unroll
        for (int nt = 0; nt < 4; nt++) {
            if constexpr (sizeof(OutT) == 2) {
                __nv_bfloat162 v0 = __floats2bfloat162_rn(acc[mt][nt][0] * alpha, acc[mt][nt][1] * alpha);
                __nv_bfloat162 v1 = __floats2bfloat162_rn(acc[mt][nt][2] * alpha, acc[mt][nt][3] * alpha);
                *(__nv_bfloat162*)(C + (size_t)(rbase + mt * 16) * LDC + cbase + nt * 8) = v0;
                *(__nv_bfloat162*)(C + (size_t)(rbase + mt * 16 + 8) * LDC + cbase + nt * 8) = v1;
            } else {
                float2 v0 = { acc[mt][nt][0] * alpha, acc[mt][nt][1] * alpha };
                float2 v1 = { acc[mt][nt][2] * alpha, acc[mt][nt][3] * alpha };
                *(float2*)(C + (size_t)(rbase + mt * 16) * LDC + cbase + nt * 8) = v0;
                *(float2*)(C + (size_t)(rbase + mt * 16 + 8) * LDC + cbase + nt * 8) = v1;
            }
        }
}

// energy(bf16) = (1/32) Q @ K^T
__global__ __launch_bounds__(256, 2) void gemm_qk_kernel()
{
    hgemm_body<512, 512, 512, 1024, 1024l * 512, 1024l * 512, 1024l * 1024, __nv_bfloat16>(
        g_qb, g_kb, g_eb, 1.0f / 32.0f);
}
// O(fp32) = attn @ V[m][n]^T
__global__ __launch_bounds__(256, 2) void gemm_av_kernel()
{
    hgemm_body<1024, 1024, 1024, 512, 1024l * 1024, 512l * 1024, 1024l * 512, float>(
        g_attn, g_vmn, g_o, 1.0f);
}

// ================= softmax: bf16 in -> bf16 out =============================
__global__ __launch_bounds__(256) void softmax_kernel()
{
    size_t row = blockIdx.x;
    const __nv_bfloat162* r = (const __nv_bfloat162*)(g_eb + row * 1024);
    int tid = threadIdx.x, wid = tid >> 5, lid = tid & 31;
    __shared__ float sm[8], ss[8];

    __nv_bfloat162 e0 = r[2 * tid], e1 = r[2 * tid + 1];
    float4 v = { __low2float(e0), __high2float(e0), __low2float(e1), __high2float(e1) };
    float m = fmaxf(fmaxf(v.x, v.y), fmaxf(v.z, v.w));
    #pragma unroll
    for (int o = 16; o; o >>= 1) m = fmaxf(m, __shfl_xor_sync(0xffffffffu, m, o));
    if (lid == 0) sm[wid] = m;
    __syncthreads();
    m = sm[0];
    #pragma unroll
    for (int i = 1; i < 8; i++) m = fmaxf(m, sm[i]);

    v.x = __expf(v.x - m); v.y = __expf(v.y - m);
    v.z = __expf(v.z - m); v.w = __expf(v.w - m);
    float s = (v.x + v.y) + (v.z + v.w);
    #pragma unroll
    for (int o = 16; o; o >>= 1) s += __shfl_xor_sync(0xffffffffu, s, o);
    if (lid == 0) ss[wid] = s;
    __syncthreads();
    s = ss[0];
    #pragma unroll
    for (int i = 1; i < 8; i++) s += ss[i];

    float inv = 1.0f / s;
    __nv_bfloat162* op = (__nv_bfloat162*)(g_attn + row * 1024) + 2 * tid;
    op[0] = __floats2bfloat162_rn(v.x * inv, v.y * inv);
    op[1] = __floats2bfloat162_rn(v.z * inv, v.w * inv);
}

// ================= epilogue: out = gamma*(Wo @ O + bo) + x ==================
__global__ __launch_bounds__(256) void epilogue_kernel(
    const float* __restrict__ x, const float* __restrict__ Wo,
    const float* __restrict__ bo, const float* __restrict__ gamma,
    float* __restrict__ out)
{
    __shared__ __align__(16) float sWo[512];
    __shared__ float sbo[64];
    int tid = threadIdx.x;
    for (int i = tid; i < 512; i += 256) sWo[i] = Wo[i];
    if (tid < 64) sbo[tid] = bo[tid];
    __syncthreads();
    float g = __ldg(gamma);

    int t = blockIdx.x * 256 + tid;
    int b = t >> 16;
    int p = t & 65535;

    float ov[8];
    size_t obase = ((size_t)b << 19) + p;
    #pragma unroll
    for (int cq = 0; cq < 8; cq++) ov[cq] = g_o[obase + ((size_t)cq << 16)];

    size_t xbase = ((size_t)b << 22) + p;
    #pragma unroll 8
    for (int o = 0; o < 64; o++) {
        float4 w0 = *(const float4*)(sWo + o * 8);
        float4 w1 = *(const float4*)(sWo + o * 8 + 4);
        float a = sbo[o];
        a += w0.x * ov[0] + w0.y * ov[1] + w0.z * ov[2] + w0.w * ov[3];
        a += w1.x * ov[4] + w1.y * ov[5] + w1.z * ov[6] + w1.w * ov[7];
        size_t idx = xbase + ((size_t)o << 16);
        out[idx] = g * a + __ldg(x + idx);
    }
}

// ================= launch ===================================================
extern "C" void kernel_launch(void* const* d_in, const int* in_sizes, int n_in,
                              void* d_out, int out_size)
{
    const float* x     = (const float*)d_in[0];
    const float* Wq    = (const float*)d_in[1];
    const float* bq    = (const float*)d_in[2];
    const float* Wk    = (const float*)d_in[3];
    const float* bk    = (const float*)d_in[4];
    const float* Wv    = (const float*)d_in[5];
    const float* bv    = (const float*)d_in[6];
    const float* Wo    = (const float*)d_in[7];
    const float* bo    = (const float*)d_in[8];
    const float* gamma = (const float*)d_in[9];
    float* out = (float*)d_out;

    cudaFuncSetAttribute(gemm_qk_kernel, cudaFuncAttributeMaxDynamicSharedMemorySize, HSMEM);
    cudaFuncSetAttribute(gemm_av_kernel, cudaFuncAttributeMaxDynamicSharedMemorySize, HSMEM);

    dim3 gq(8, 16, 8);
    qkv_kernel<<<gq, 256>>>(x, Wq, bq, Wk, bk, Wv, bv);

    dim3 gqk(8, 8, 8);
    gemm_qk_kernel<<<gqk, 256, HSMEM>>>();

    softmax_kernel<<<8 * 1024, 256>>>();

    dim3 gav(4, 8, 8);
    gemm_av_kernel<<<gav, 256, HSMEM>>>();

    epilogue_kernel<<<2048, 256>>>(x, Wo, bo, gamma, out);
}